// round 4
// baseline (speedup 1.0000x reference)
#include <cuda_runtime.h>
#include <cstdint>

typedef unsigned long long ull;

// Packed fp32x2 FMA (sm_100+; ptxas never emits this from plain C++).
__device__ __forceinline__ ull fma2(ull a, ull b, ull c) {
    ull d;
    asm("fma.rn.f32x2 %0, %1, %2, %3;" : "=l"(d) : "l"(a), "l"(b), "l"(c));
    return d;
}
__device__ __forceinline__ ull dup2(float x) {
    ull d;
    asm("mov.b64 %0, {%1, %1};" : "=l"(d) : "f"(x));
    return d;
}
__device__ __forceinline__ void unpack2(ull v, float& lo, float& hi) {
    asm("mov.b64 {%0, %1}, %2;" : "=f"(lo), "=f"(hi) : "l"(v));
}
__device__ __forceinline__ ull pack2(float lo, float hi) {
    ull d;
    asm("mov.b64 %0, {%1, %2};" : "=l"(d) : "f"(lo), "f"(hi));
    return d;
}

// b0[r,f,n] = sum_m CG0[r,m]*A[f,m,n]  (r=0..7)
// b1[r,f,n] = sum_m CG1[r,m]*A[f,m,n]  (r=0..23)
// r (32 total) split 16/16 across two CTAs (blockIdx.x) for occupancy; the
// twin CTA re-reads A out of L2. Accumulators packed along r; CG transposed
// [m][r] in shared so multiplier pairs load packed.
template <int M, int F>
__global__ void __launch_bounds__(256, 4)
sym_kernel(const float* __restrict__ A,
           const float* __restrict__ cg0,
           const float* __restrict__ cg1,
           float* __restrict__ out0,
           float* __restrict__ out1) {
    const int rh = blockIdx.x;                   // 0 or 1: r in [rh*16, rh*16+16)
    __shared__ __align__(16) float cgs[M][16];
    const int tid = threadIdx.x;
    for (int i = tid; i < M * 16; i += 256) {
        const int mi = i >> 4;
        const int j = i & 15;
        const int r = rh * 16 + j;
        cgs[mi][j] = (r < 8) ? cg0[r * M + mi] : cg1[(r - 8) * M + mi];
    }
    __syncthreads();

    const int f = blockIdx.y;
    const int n0 = blockIdx.z * 512 + tid * 2;   // even, <= 1022
    const float* aptr = A + (size_t)f * (M * 1024) + n0;

    // acc[p][j]: packed (b[base+2p], b[base+2p+1]) at column n0+j
    ull acc[8][2];
#pragma unroll
    for (int p = 0; p < 8; p++) { acc[p][0] = 0ull; acc[p][1] = 0ull; }

    // Prefetch ring, depth 3 (M >= 9 always).
    float2 pf0 = *reinterpret_cast<const float2*>(aptr);
    float2 pf1 = *reinterpret_cast<const float2*>(aptr + 1024);
    float2 pf2 = *reinterpret_cast<const float2*>(aptr + 2048);

#pragma unroll 3
    for (int mi = 0; mi < M; ++mi) {
        const float2 a = pf0;
        pf0 = pf1;
        pf1 = pf2;
        if (mi + 3 < M)
            pf2 = *reinterpret_cast<const float2*>(aptr + (size_t)(mi + 3) * 1024);
        const ull a0 = dup2(a.x);
        const ull a1 = dup2(a.y);
        const ulonglong2* crow = reinterpret_cast<const ulonglong2*>(&cgs[mi][0]);
#pragma unroll
        for (int q = 0; q < 4; q++) {
            // One LDS.128 (broadcast) = 2 packed cg pairs = 4 r values.
            const ulonglong2 c = crow[q];
            acc[2 * q][0]     = fma2(c.x, a0, acc[2 * q][0]);
            acc[2 * q][1]     = fma2(c.x, a1, acc[2 * q][1]);
            acc[2 * q + 1][0] = fma2(c.y, a0, acc[2 * q + 1][0]);
            acc[2 * q + 1][1] = fma2(c.y, a1, acc[2 * q + 1][1]);
        }
    }

    // Epilogue: 2x2 register transpose per pair -> coalesced STG.64 per r.
    const int rbase = rh * 16;
#pragma unroll
    for (int p = 0; p < 8; p++) {
        float x0, y0, x1, y1;
        unpack2(acc[p][0], x0, y0);
        unpack2(acc[p][1], x1, y1);
        const ull v0 = pack2(x0, x1);
        const ull v1 = pack2(y0, y1);
        const int r0 = rbase + 2 * p;
        const int r1 = r0 + 1;
        if (r0 < 8) {
            *reinterpret_cast<ull*>(out0 + ((size_t)r0 * F + f) * 1024 + n0) = v0;
        } else {
            *reinterpret_cast<ull*>(out1 + ((size_t)(r0 - 8) * F + f) * 1024 + n0) = v0;
        }
        if (r1 < 8) {
            *reinterpret_cast<ull*>(out0 + ((size_t)r1 * F + f) * 1024 + n0) = v1;
        } else {
            *reinterpret_cast<ull*>(out1 + ((size_t)(r1 - 8) * F + f) * 1024 + n0) = v1;
        }
    }
}

extern "C" void kernel_launch(void* const* d_in, const int* in_sizes, int n_in,
                              void* d_out, int out_size) {
    (void)in_sizes; (void)n_in; (void)out_size;
    const float* A2_l11  = (const float*)d_in[0];   // [1024,  9, 1024]
    const float* A2_l22  = (const float*)d_in[1];   // [1024, 25, 1024]
    const float* A2_l33  = (const float*)d_in[2];   // [1024, 49, 1024]
    const float* A3_l111 = (const float*)d_in[3];   // [ 512, 27, 1024]
    const float* A3_l211 = (const float*)d_in[4];   // [ 512, 45, 1024]
    const float* CG0_0 = (const float*)d_in[5];
    const float* CG0_1 = (const float*)d_in[6];
    const float* CG0_2 = (const float*)d_in[7];
    const float* CG0_3 = (const float*)d_in[8];
    const float* CG0_4 = (const float*)d_in[9];
    const float* CG1_0 = (const float*)d_in[10];
    const float* CG1_1 = (const float*)d_in[11];
    const float* CG1_2 = (const float*)d_in[12];
    const float* CG1_3 = (const float*)d_in[13];
    const float* CG1_4 = (const float*)d_in[14];
    float* out = (float*)d_out;

    // Output region offsets (elements), tuple order b0(5) then b1(5):
    constexpr size_t o0_0 = 0;
    constexpr size_t o0_1 = o0_0 + (size_t)8 * 1024 * 1024;
    constexpr size_t o0_2 = o0_1 + (size_t)8 * 1024 * 1024;
    constexpr size_t o0_3 = o0_2 + (size_t)8 * 1024 * 1024;
    constexpr size_t o0_4 = o0_3 + (size_t)8 * 512 * 1024;
    constexpr size_t o1_0 = o0_4 + (size_t)8 * 512 * 1024;
    constexpr size_t o1_1 = o1_0 + (size_t)24 * 1024 * 1024;
    constexpr size_t o1_2 = o1_1 + (size_t)24 * 1024 * 1024;
    constexpr size_t o1_3 = o1_2 + (size_t)24 * 1024 * 1024;
    constexpr size_t o1_4 = o1_3 + (size_t)24 * 512 * 1024;

    const dim3 blk(256);
    // grid: x = r-half (adjacent bids share A via L2), y = f, z = n-tile
    sym_kernel<9, 1024><<<dim3(2, 1024, 2), blk>>>(A2_l11,  CG0_0, CG1_0, out + o0_0, out + o1_0);
    sym_kernel<25, 1024><<<dim3(2, 1024, 2), blk>>>(A2_l22, CG0_1, CG1_1, out + o0_1, out + o1_1);
    sym_kernel<49, 1024><<<dim3(2, 1024, 2), blk>>>(A2_l33, CG0_2, CG1_2, out + o0_2, out + o1_2);
    sym_kernel<27, 512><<<dim3(2, 512, 2), blk>>>(A3_l111, CG0_3, CG1_3, out + o0_3, out + o1_3);
    sym_kernel<45, 512><<<dim3(2, 512, 2), blk>>>(A3_l211, CG0_4, CG1_4, out + o0_4, out + o1_4);
}

// round 6
// speedup vs baseline: 1.6084x; 1.6084x over previous
#include <cuda_runtime.h>
#include <cstdint>

typedef unsigned long long ull;

// Packed fp32x2 FMA (sm_100+; ptxas never emits this from plain C++).
__device__ __forceinline__ ull fma2(ull a, ull b, ull c) {
    ull d;
    asm("fma.rn.f32x2 %0, %1, %2, %3;" : "=l"(d) : "l"(a), "l"(b), "l"(c));
    return d;
}

// b0[r,f,n] = sum_m CG0[r,m]*A[f,m,n]  (r=0..7)
// b1[r,f,n] = sum_m CG1[r,m]*A[f,m,n]  (r=0..23)
// Layout: each thread owns 4 n-columns (one LDG.128 per mi = two packed f32x2
// A operands, no dup MOVs). CG stored in shared as duplicated pairs so one
// broadcast LDS.128 feeds 2 r x 4 n = 8 FFMA2. r split 16/16 across paired
// CTAs (twin re-reads A from L2). A loads batched 4-deep for MLP=4.
template <int M, int F>
__global__ void __launch_bounds__(256, 2)
sym_kernel(const float* __restrict__ A,
           const float* __restrict__ cg0,
           const float* __restrict__ cg1,
           float* __restrict__ out0,
           float* __restrict__ out1) {
    const int rh = blockIdx.x;                    // r in [rh*16, rh*16+16)
    // cgd[mi][j] = dup2(CG[rh*16+j, mi]); consecutive j pairs read as LDS.128.
    __shared__ __align__(16) ull cgd[M][16];
    const int tid = threadIdx.x;
    for (int i = tid; i < M * 16; i += 256) {
        const int mi = i >> 4;
        const int j = i & 15;
        const int r = rh * 16 + j;
        const float c = (r < 8) ? cg0[r * M + mi] : cg1[(r - 8) * M + mi];
        ull p = (ull)__float_as_uint(c);
        cgd[mi][j] = p | (p << 32);
    }
    __syncthreads();

    const int f = blockIdx.y;
    const int n0 = tid * 4;                        // 16B-aligned column group
    const float* aptr = A + (size_t)f * (M * 1024) + n0;

    // acc[j][k]: packed f32x2 for r = rh*16 + j, n-pair k (n0+2k, n0+2k+1)
    ull acc[16][2];
#pragma unroll
    for (int j = 0; j < 16; j++) { acc[j][0] = 0ull; acc[j][1] = 0ull; }

    constexpr int M4 = (M / 4) * 4;
    constexpr int TAIL = M - M4;

    for (int mc = 0; mc < M4; mc += 4) {
        // Front-batched independent LDG.128s -> MLP = 4.
        ulonglong2 buf[4];
#pragma unroll
        for (int j = 0; j < 4; j++)
            buf[j] = *reinterpret_cast<const ulonglong2*>(aptr + (size_t)(mc + j) * 1024);
#pragma unroll
        for (int j = 0; j < 4; j++) {
            const ull alo = buf[j].x;              // (a[n0],   a[n0+1])
            const ull ahi = buf[j].y;              // (a[n0+2], a[n0+3])
            const ulonglong2* crow = reinterpret_cast<const ulonglong2*>(&cgd[mc + j][0]);
#pragma unroll
            for (int q = 0; q < 8; q++) {
                const ulonglong2 c = crow[q];      // dup cg for r=2q, 2q+1
                acc[2 * q][0]     = fma2(c.x, alo, acc[2 * q][0]);
                acc[2 * q][1]     = fma2(c.x, ahi, acc[2 * q][1]);
                acc[2 * q + 1][0] = fma2(c.y, alo, acc[2 * q + 1][0]);
                acc[2 * q + 1][1] = fma2(c.y, ahi, acc[2 * q + 1][1]);
            }
        }
    }
    if (TAIL > 0) {
        ulonglong2 buf[TAIL > 0 ? TAIL : 1];
#pragma unroll
        for (int j = 0; j < TAIL; j++)
            buf[j] = *reinterpret_cast<const ulonglong2*>(aptr + (size_t)(M4 + j) * 1024);
#pragma unroll
        for (int j = 0; j < TAIL; j++) {
            const ull alo = buf[j].x;
            const ull ahi = buf[j].y;
            const ulonglong2* crow = reinterpret_cast<const ulonglong2*>(&cgd[M4 + j][0]);
#pragma unroll
            for (int q = 0; q < 8; q++) {
                const ulonglong2 c = crow[q];
                acc[2 * q][0]     = fma2(c.x, alo, acc[2 * q][0]);
                acc[2 * q][1]     = fma2(c.x, ahi, acc[2 * q][1]);
                acc[2 * q + 1][0] = fma2(c.y, alo, acc[2 * q + 1][0]);
                acc[2 * q + 1][1] = fma2(c.y, ahi, acc[2 * q + 1][1]);
            }
        }
    }

    // Epilogue: one STG.128 per r, coalesced along n.
    const int rbase = rh * 16;
#pragma unroll
    for (int j = 0; j < 16; j++) {
        const int r = rbase + j;
        ulonglong2 v;
        v.x = acc[j][0];
        v.y = acc[j][1];
        float* dst = (r < 8)
            ? (out0 + ((size_t)r * F + f) * 1024 + n0)
            : (out1 + ((size_t)(r - 8) * F + f) * 1024 + n0);
        *reinterpret_cast<ulonglong2*>(dst) = v;
    }
}

extern "C" void kernel_launch(void* const* d_in, const int* in_sizes, int n_in,
                              void* d_out, int out_size) {
    (void)in_sizes; (void)n_in; (void)out_size;
    const float* A2_l11  = (const float*)d_in[0];   // [1024,  9, 1024]
    const float* A2_l22  = (const float*)d_in[1];   // [1024, 25, 1024]
    const float* A2_l33  = (const float*)d_in[2];   // [1024, 49, 1024]
    const float* A3_l111 = (const float*)d_in[3];   // [ 512, 27, 1024]
    const float* A3_l211 = (const float*)d_in[4];   // [ 512, 45, 1024]
    const float* CG0_0 = (const float*)d_in[5];
    const float* CG0_1 = (const float*)d_in[6];
    const float* CG0_2 = (const float*)d_in[7];
    const float* CG0_3 = (const float*)d_in[8];
    const float* CG0_4 = (const float*)d_in[9];
    const float* CG1_0 = (const float*)d_in[10];
    const float* CG1_1 = (const float*)d_in[11];
    const float* CG1_2 = (const float*)d_in[12];
    const float* CG1_3 = (const float*)d_in[13];
    const float* CG1_4 = (const float*)d_in[14];
    float* out = (float*)d_out;

    // Output region offsets (elements), tuple order b0(5) then b1(5):
    constexpr size_t o0_0 = 0;
    constexpr size_t o0_1 = o0_0 + (size_t)8 * 1024 * 1024;
    constexpr size_t o0_2 = o0_1 + (size_t)8 * 1024 * 1024;
    constexpr size_t o0_3 = o0_2 + (size_t)8 * 1024 * 1024;
    constexpr size_t o0_4 = o0_3 + (size_t)8 * 512 * 1024;
    constexpr size_t o1_0 = o0_4 + (size_t)8 * 512 * 1024;
    constexpr size_t o1_1 = o1_0 + (size_t)24 * 1024 * 1024;
    constexpr size_t o1_2 = o1_1 + (size_t)24 * 1024 * 1024;
    constexpr size_t o1_3 = o1_2 + (size_t)24 * 1024 * 1024;
    constexpr size_t o1_4 = o1_3 + (size_t)24 * 512 * 1024;

    const dim3 blk(256);
    // grid: x = r-half (adjacent bids co-resident -> share A via L2), y = f
    sym_kernel<9, 1024><<<dim3(2, 1024), blk>>>(A2_l11,  CG0_0, CG1_0, out + o0_0, out + o1_0);
    sym_kernel<25, 1024><<<dim3(2, 1024), blk>>>(A2_l22, CG0_1, CG1_1, out + o0_1, out + o1_1);
    sym_kernel<49, 1024><<<dim3(2, 1024), blk>>>(A2_l33, CG0_2, CG1_2, out + o0_2, out + o1_2);
    sym_kernel<27, 512><<<dim3(2, 512), blk>>>(A3_l111, CG0_3, CG1_3, out + o0_3, out + o1_3);
    sym_kernel<45, 512><<<dim3(2, 512), blk>>>(A3_l211, CG0_4, CG1_4, out + o0_4, out + o1_4);
}